// round 13
// baseline (speedup 1.0000x reference)
#include <cuda_runtime.h>
#include <cuda_fp16.h>
#include <cstdint>

#define DIM     256
#define BT      32768
#define NCODE   2048
#define MARGIN  3.0f
#define RCAP    6                  // candidates per row per tile record
#define MBLK    128
#define NTILE   128
#define N_TILES (NCODE / NTILE)    // 16
#define KC      64                 // dims per K-chunk
#define N_KC    (DIM / KC)         // 4
#define STAGE_BYTES 32768          // A 16KB + B 16KB

// GEMM smem layout (relative to 1KB-aligned base)
#define OFF_BUF  0                 // 2 stages x 32 KB
#define OFF_KEY  65536             // u32[128]
#define OFF_CNT  66048             // int[128]
#define OFF_CAND 66560             // int[128][RCAP] = 3072
#define SMEM_BYTES (66560 + 128 * RCAP * 4 + 1024)

// ---------------------------------------------------------------------------
__device__ __half g_xh [(size_t)BT * DIM];      // 16 MB
__device__ __half g_cbh[(size_t)NCODE * DIM];   // 1 MB
__device__ float g_c2[NCODE];
__device__ int   g_rec[(size_t)BT * N_TILES * 8];   // 16 MB: {minf,cnt,cand[6]}
__device__ float g_partial[BT];
__device__ float g_dummy[BT + 1];

// ---------------------------------------------------------------------------
__device__ __forceinline__ uint32_t smem_u32(const void* p) {
    uint32_t a;
    asm("{ .reg .u64 t; cvta.to.shared.u64 t, %1; cvt.u32.u64 %0, t; }"
        : "=r"(a) : "l"(p));
    return a;
}

#define SWZ(o) ((o) ^ (((o) >> 3) & 0x70))

__device__ __forceinline__ void cp16(uint32_t d, const void* s) {
    asm volatile("cp.async.cg.shared.global [%0], [%1], 16;\n"
                 :: "r"(d), "l"(__cvta_generic_to_global(s)));
}
__device__ __forceinline__ void cp_commit() {
    asm volatile("cp.async.commit_group;\n" ::: "memory");
}
template <int N> __device__ __forceinline__ void cp_wait() {
    asm volatile("cp.async.wait_group %0;\n" :: "n"(N) : "memory");
}

__device__ __forceinline__ void ldm_x4(uint32_t& r0, uint32_t& r1,
                                       uint32_t& r2, uint32_t& r3, uint32_t a) {
    asm volatile("ldmatrix.sync.aligned.m8n8.x4.shared.b16 {%0,%1,%2,%3}, [%4];"
                 : "=r"(r0), "=r"(r1), "=r"(r2), "=r"(r3) : "r"(a));
}

// fp16 inputs + fp16 accumulators (2 D-regs) — halves accumulator registers.
__device__ __forceinline__ void mma_f16(uint32_t* d, uint32_t a0, uint32_t a1,
                                        uint32_t a2, uint32_t a3,
                                        uint32_t b0, uint32_t b1) {
    asm volatile(
        "mma.sync.aligned.m16n8k16.row.col.f16.f16.f16.f16 "
        "{%0,%1}, {%2,%3,%4,%5}, {%6,%7}, {%0,%1};"
        : "+r"(d[0]), "+r"(d[1])
        : "r"(a0), "r"(a1), "r"(a2), "r"(a3), "r"(b0), "r"(b1));
}

__device__ __forceinline__ uint32_t fkey(float f) {
    uint32_t u = __float_as_uint(f);
    return (u & 0x80000000u) ? ~u : (u | 0x80000000u);
}
__device__ __forceinline__ float fdec(uint32_t k) {
    uint32_t u = (k & 0x80000000u) ? (k ^ 0x80000000u) : ~k;
    return __uint_as_float(u);
}

// ---------------------------------------------------------------------------
__global__ void tofp16_kernel(const float* __restrict__ in,
                              __half* __restrict__ outp, int n4) {
    int i = blockIdx.x * blockDim.x + threadIdx.x;
    if (i >= n4) return;
    float4 v = ((const float4*)in)[i];
    ((__half2*)outp)[2 * i]     = __floats2half2_rn(v.x, v.y);
    ((__half2*)outp)[2 * i + 1] = __floats2half2_rn(v.z, v.w);
}

__global__ void c2_kernel(const float* __restrict__ cb, int N) {
    int warp = (blockIdx.x * blockDim.x + threadIdx.x) >> 5;
    int lane = threadIdx.x & 31;
    if (warp >= N) return;
    const float4* row = (const float4*)(cb + (size_t)warp * DIM);
    float s = 0.f;
#pragma unroll
    for (int i = 0; i < 2; i++) {
        float4 v = row[lane + i * 32];
        s += v.x * v.x + v.y * v.y + v.z * v.z + v.w * v.w;
    }
#pragma unroll
    for (int o = 16; o > 0; o >>= 1) s += __shfl_xor_sync(0xffffffffu, s, o);
    if (lane == 0) g_c2[warp] = s;
}

// ---------------------------------------------------------------------------
// stage one K-chunk: A[128 x 64] + B[128 x 64] fp16 (16KB each)
// ---------------------------------------------------------------------------
__device__ __forceinline__ void stage_ab(uint32_t dst, int m0, int n0,
                                         int kc, int tid) {
#pragma unroll
    for (int i = 0; i < 4; i++) {
        int idx = tid + (i << 8);
        int c16 = idx & 7;
        int row = idx >> 3;
        uint32_t off = SWZ((uint32_t)(row * 128 + c16 * 16));
        cp16(dst + off,
             g_xh + (size_t)(m0 + row) * DIM + kc * KC + c16 * 8);
        cp16(dst + 16384 + off,
             g_cbh + (size_t)(n0 + row) * DIM + kc * KC + c16 * 8);
    }
    cp_commit();
}

// ---------------------------------------------------------------------------
// GEMM kernel: one 128x128 tile per CTA, 8 warps (4M x 2N), warp tile 32x64.
// fp16 accum + single-buffered fragments -> low regs -> 3 CTAs/SM.
// ---------------------------------------------------------------------------
__global__ void __launch_bounds__(256, 3)
gemm_tile_kernel() {
    extern __shared__ char smraw[];
    const uint32_t sb0   = smem_u32(smraw);
    const uint32_t sbase = (sb0 + 1023) & ~1023u;
    char* smp = smraw + (sbase - sb0);

    uint32_t* rowkey = (uint32_t*)(smp + OFF_KEY);
    int*      cnt    = (int*)     (smp + OFF_CNT);
    int*      cand   = (int*)     (smp + OFF_CAND);

    const int tid  = threadIdx.x;
    const int wid  = tid >> 5;
    const int lane = tid & 31;
    const int m0   = blockIdx.x * MBLK;
    const int n0   = blockIdx.y * NTILE;
    const int wm   = (wid & 3) * 32;
    const int wn   = (wid >> 2) * 64;
    const int lrow = lane & 15;
    const int lcol = (lane >> 4) << 4;
    const int g    = lane >> 2;
    const int tg   = lane & 3;

    // Swizzled row bases. Addr(kb) = base ^ kb (kb hits swizzle bits 4..6).
    const uint32_t swzA0 = SWZ((uint32_t)((wm + lrow) * 128)) ^ (uint32_t)lcol;
    const uint32_t swzA1 = SWZ((uint32_t)((wm + 16 + lrow) * 128)) ^ (uint32_t)lcol;
    uint32_t swzB[4];
#pragma unroll
    for (int jn = 0; jn < 4; jn++)
        swzB[jn] = SWZ((uint32_t)((wn + jn * 16 + lrow) * 128)) ^ (uint32_t)lcol;

    if (tid < 128) { rowkey[tid] = 0xFFFFFFFFu; cnt[tid] = 0; }

    stage_ab(sbase + OFF_BUF, m0, n0, 0, tid);

    // fp16x2 accumulators: [im][jn][h], each reg = 2 adjacent cols
    uint32_t acc[2][8][2];
#pragma unroll
    for (int a = 0; a < 2; a++)
#pragma unroll
        for (int b = 0; b < 8; b++) { acc[a][b][0] = 0u; acc[a][b][1] = 0u; }

    uint32_t fa0[4], fa1[4], fb[4][4];   // single-buffered fragments

#pragma unroll
    for (int kc = 0; kc < N_KC; kc++) {
        cp_wait<0>();
        __syncthreads();
        if (kc + 1 < N_KC)
            stage_ab(sbase + OFF_BUF + ((kc + 1) & 1) * STAGE_BYTES,
                     m0, n0, kc + 1, tid);

        const uint32_t pa = sbase + OFF_BUF + (kc & 1) * STAGE_BYTES;
        const uint32_t pb = pa + 16384;

#pragma unroll
        for (int ks = 0; ks < 4; ks++) {
            const uint32_t kb = (uint32_t)(ks * 32);
            ldm_x4(fa0[0], fa0[1], fa0[2], fa0[3], pa + (swzA0 ^ kb));
            ldm_x4(fa1[0], fa1[1], fa1[2], fa1[3], pa + (swzA1 ^ kb));
#pragma unroll
            for (int jn = 0; jn < 4; jn++)
                ldm_x4(fb[jn][0], fb[jn][1], fb[jn][2], fb[jn][3],
                       pb + (swzB[jn] ^ kb));
#pragma unroll
            for (int jn = 0; jn < 4; jn++) {
                mma_f16(acc[0][jn * 2],     fa0[0], fa0[1], fa0[2], fa0[3], fb[jn][0], fb[jn][2]);
                mma_f16(acc[0][jn * 2 + 1], fa0[0], fa0[1], fa0[2], fa0[3], fb[jn][1], fb[jn][3]);
                mma_f16(acc[1][jn * 2],     fa1[0], fa1[1], fa1[2], fa1[3], fb[jn][0], fb[jn][2]);
                mma_f16(acc[1][jn * 2 + 1], fa1[0], fa1[1], fa1[2], fa1[3], fb[jn][1], fb[jn][3]);
            }
        }
    }

    // ---- Epilogue (once): tile-local min + candidates -----------------------
    float c2r[8][2];
#pragma unroll
    for (int jn = 0; jn < 8; jn++)
#pragma unroll
        for (int q = 0; q < 2; q++)
            c2r[jn][q] = __ldg(&g_c2[n0 + wn + jn * 8 + tg * 2 + q]);

#pragma unroll
    for (int im = 0; im < 2; im++)
#pragma unroll
        for (int h = 0; h < 2; h++) {
            int r = wm + im * 16 + h * 8 + g;
            float mn = 3.4e38f;
#pragma unroll
            for (int jn = 0; jn < 8; jn++) {
                float2 dv = __half22float2(*(__half2*)&acc[im][jn][h]);
                mn = fminf(mn, fmaf(-2.f, dv.x, c2r[jn][0]));
                mn = fminf(mn, fmaf(-2.f, dv.y, c2r[jn][1]));
            }
            mn = fminf(mn, __shfl_xor_sync(0xffffffffu, mn, 1));
            mn = fminf(mn, __shfl_xor_sync(0xffffffffu, mn, 2));
            if (tg == 0) atomicMin(&rowkey[r], fkey(mn));
        }
    __syncthreads();

#pragma unroll
    for (int im = 0; im < 2; im++)
#pragma unroll
        for (int h = 0; h < 2; h++) {
            int r = wm + im * 16 + h * 8 + g;
            float thr = fdec(rowkey[r]) + MARGIN;
#pragma unroll
            for (int jn = 0; jn < 8; jn++) {
                float2 dv = __half22float2(*(__half2*)&acc[im][jn][h]);
#pragma unroll
                for (int q = 0; q < 2; q++) {
                    float sc = fmaf(-2.f, q ? dv.y : dv.x, c2r[jn][q]);
                    if (sc < thr) {
                        int p = atomicAdd(&cnt[r], 1);
                        if (p < RCAP)
                            cand[r * RCAP + p] = n0 + wn + jn * 8 + tg * 2 + q;
                    }
                }
            }
        }
    __syncthreads();

    // ---- Write 32B record per row ------------------------------------------
    if (tid < 128) {
        int rec[8];
        rec[0] = __float_as_int(fdec(rowkey[tid]));
        rec[1] = cnt[tid];
#pragma unroll
        for (int j = 0; j < RCAP; j++) rec[2 + j] = cand[tid * RCAP + j];
        int* dst = g_rec + ((size_t)(m0 + tid) * N_TILES + blockIdx.y) * 8;
        *(int4*)(dst)     = make_int4(rec[0], rec[1], rec[2], rec[3]);
        *(int4*)(dst + 4) = make_int4(rec[4], rec[5], rec[6], rec[7]);
    }
}

// ---------------------------------------------------------------------------
// Combine: per token, global min over tiles, exact fp32 rescore of pruned
// candidate set, gather + SSE partial + index. 128 threads per token.
// ---------------------------------------------------------------------------
__global__ void __launch_bounds__(128)
combine_kernel(const float* __restrict__ x, const float* __restrict__ cb,
               float* __restrict__ out_q, float* __restrict__ out_idx) {
    __shared__ int   recs[N_TILES * 8];
    __shared__ float xs[DIM];
    __shared__ float sgmin;
    __shared__ int   clist[N_TILES * RCAP];
    __shared__ int   ftile[N_TILES];
    __shared__ int   ccnt, fcnt;
    __shared__ unsigned long long sbest;

    const int t = blockIdx.x, tid = threadIdx.x;
    const int wid = tid >> 5, lane = tid & 31;

    if (tid < 32) ((int4*)recs)[tid] = ((const int4*)(g_rec + (size_t)t * N_TILES * 8))[tid];
    ((float2*)xs)[tid] = ((const float2*)(x + (size_t)t * DIM))[tid];
    if (tid == 0) { ccnt = 0; fcnt = 0; sbest = ~0ull; }
    __syncthreads();

    if (tid == 0) {
        float gm = 3.4e38f;
#pragma unroll
        for (int i = 0; i < N_TILES; i++)
            gm = fminf(gm, __int_as_float(recs[i * 8]));
        sgmin = gm;
    }
    __syncthreads();
    const float glim = sgmin + MARGIN;

    if (tid < N_TILES) {
        float tmin = __int_as_float(recs[tid * 8]);
        if (tmin <= glim) {
            int c = recs[tid * 8 + 1];
            if (c <= RCAP) {
                for (int j = 0; j < c; j++) {
                    int p = atomicAdd(&ccnt, 1);
                    clist[p] = recs[tid * 8 + 2 + j];
                }
            } else {
                int p = atomicAdd(&fcnt, 1);
                ftile[p] = tid;
            }
        }
    }
    __syncthreads();

    // exact rescore: warp per candidate
    const int nc = ccnt;
    for (int ci = wid; ci < nc; ci += 4) {
        int n = clist[ci];
        const float* cr = cb + (size_t)n * DIM;
        float dot = 0.f;
#pragma unroll
        for (int j = 0; j < 8; j++)
            dot = fmaf(xs[lane + j * 32], cr[lane + j * 32], dot);
#pragma unroll
        for (int o = 16; o > 0; o >>= 1)
            dot += __shfl_xor_sync(0xffffffffu, dot, o);
        if (lane == 0) {
            float sv = __ldg(&g_c2[n]) - 2.f * dot;
            unsigned long long key =
                ((unsigned long long)fkey(sv) << 32) | (uint32_t)n;
            atomicMin(&sbest, key);
        }
    }

    // overflowed tiles (rare): exact rescan of all 128 codes in the tile
    const int nf = fcnt;
    for (int fi = 0; fi < nf; fi++) {
        int base = ftile[fi] * NTILE;
        for (int cc = wid; cc < NTILE; cc += 4) {
            int n = base + cc;
            const float* cr = cb + (size_t)n * DIM;
            float dot = 0.f;
#pragma unroll
            for (int j = 0; j < 8; j++)
                dot = fmaf(xs[lane + j * 32], cr[lane + j * 32], dot);
#pragma unroll
            for (int o = 16; o > 0; o >>= 1)
                dot += __shfl_xor_sync(0xffffffffu, dot, o);
            if (lane == 0) {
                float sv = __ldg(&g_c2[n]) - 2.f * dot;
                unsigned long long key =
                    ((unsigned long long)fkey(sv) << 32) | (uint32_t)n;
                atomicMin(&sbest, key);
            }
        }
    }
    __syncthreads();
    const int best = (int)(sbest & 0xFFFFFFFFull);

    // gather + SSE partial
    float2 c2v = ((const float2*)(cb + (size_t)best * DIM))[tid];
    ((float2*)(out_q + (size_t)t * DIM))[tid] = c2v;
    float2 xv = ((const float2*)xs)[tid];
    float dx = xv.x - c2v.x, dy = xv.y - c2v.y;
    float d = dx * dx + dy * dy;
#pragma unroll
    for (int o = 16; o > 0; o >>= 1) d += __shfl_xor_sync(0xffffffffu, d, o);
    __shared__ float red[4];
    if (lane == 0) red[wid] = d;
    __syncthreads();
    if (tid == 0) {
        g_partial[t] = red[0] + red[1] + red[2] + red[3];
        out_idx[t]   = (float)best;
    }
}

// ---------------------------------------------------------------------------
__global__ void loss_kernel(float* __restrict__ out_loss, int n4, float inv_count) {
    __shared__ float red[32];
    const int tid = threadIdx.x;
    float s = 0.f;
    const float4* p4 = (const float4*)g_partial;
    for (int i = tid; i < n4; i += 1024) {
        float4 v = p4[i];
        s += v.x + v.y + v.z + v.w;
    }
#pragma unroll
    for (int o = 16; o > 0; o >>= 1) s += __shfl_xor_sync(0xffffffffu, s, o);
    if ((tid & 31) == 0) red[tid >> 5] = s;
    __syncthreads();
    if (tid < 32) {
        float v = red[tid];
#pragma unroll
        for (int o = 16; o > 0; o >>= 1) v += __shfl_xor_sync(0xffffffffu, v, o);
        if (tid == 0) *out_loss = 2.f * v * inv_count;
    }
}

// ---------------------------------------------------------------------------
extern "C" void kernel_launch(void* const* d_in, const int* in_sizes, int n_in,
                              void* d_out, int out_size) {
    const float* x  = (const float*)d_in[0];
    const float* cb = (const float*)d_in[1];
    float* out = (float*)d_out;

    const int bt = in_sizes[0] / DIM;   // 32768
    const int nc = in_sizes[1] / DIM;   // 2048

    const long long need = (long long)bt * DIM + bt + 1;
    const bool full_layout = ((long long)out_size >= need);
    float* out_idx  = full_layout ? (out + (size_t)bt * DIM) : g_dummy;
    float* out_loss = full_layout ? (out + (size_t)bt * DIM + bt) : (g_dummy + BT);

    __half* xh;  cudaGetSymbolAddress((void**)&xh,  g_xh);
    __half* cbh; cudaGetSymbolAddress((void**)&cbh, g_cbh);

    const int nx4 = bt * DIM / 4;
    const int nc4 = nc * DIM / 4;
    tofp16_kernel<<<(nx4 + 255) / 256, 256>>>(x,  xh,  nx4);
    tofp16_kernel<<<(nc4 + 255) / 256, 256>>>(cb, cbh, nc4);
    c2_kernel<<<(nc + 7) / 8, 256>>>(cb, nc);

    cudaFuncSetAttribute(gemm_tile_kernel,
                         cudaFuncAttributeMaxDynamicSharedMemorySize, SMEM_BYTES);
    dim3 grid(bt / MBLK, nc / NTILE);
    gemm_tile_kernel<<<grid, 256, SMEM_BYTES>>>();

    combine_kernel<<<bt, 128>>>(x, cb, out, out_idx);
    loss_kernel<<<1, 1024>>>(out_loss, bt / 4, 1.f / ((float)bt * (float)DIM));
}

// round 14
// speedup vs baseline: 1.0116x; 1.0116x over previous
#include <cuda_runtime.h>
#include <cuda_fp16.h>
#include <cstdint>

#define DIM     256
#define BT      32768
#define NCODE   2048
#define MARGIN  3.0f
#define RCAP    6                  // candidates per row per tile record
#define MBLK    128
#define NTILE   256
#define N_TILES (NCODE / NTILE)    // 8
#define KC      64                 // dims per K-chunk
#define N_KC    (DIM / KC)         // 4
#define STAGE_BYTES 49152          // A 16KB + B 32KB

// GEMM smem layout (relative to 1KB-aligned base)
#define OFF_BUF  0                 // 2 stages x 48 KB
#define OFF_KEY  98304             // u32[128]
#define OFF_CNT  98816             // int[128]
#define OFF_CAND 99328             // int[128][RCAP] = 3072
#define SMEM_BYTES (99328 + 128 * RCAP * 4 + 1024)

// ---------------------------------------------------------------------------
__device__ __half g_xh [(size_t)BT * DIM];      // 16 MB
__device__ __half g_cbh[(size_t)NCODE * DIM];   // 1 MB
__device__ float g_c2[NCODE];
__device__ int   g_rec[(size_t)BT * N_TILES * 8];   // 8 MB: {minf,cnt,cand[6]}
__device__ float g_partial[BT];
__device__ float g_dummy[BT + 1];

// ---------------------------------------------------------------------------
__device__ __forceinline__ uint32_t smem_u32(const void* p) {
    uint32_t a;
    asm("{ .reg .u64 t; cvta.to.shared.u64 t, %1; cvt.u32.u64 %0, t; }"
        : "=r"(a) : "l"(p));
    return a;
}

#define SWZ(o) ((o) ^ (((o) >> 3) & 0x70))

__device__ __forceinline__ void cp16(uint32_t d, const void* s) {
    asm volatile("cp.async.cg.shared.global [%0], [%1], 16;\n"
                 :: "r"(d), "l"(__cvta_generic_to_global(s)));
}
__device__ __forceinline__ void cp_commit() {
    asm volatile("cp.async.commit_group;\n" ::: "memory");
}
template <int N> __device__ __forceinline__ void cp_wait() {
    asm volatile("cp.async.wait_group %0;\n" :: "n"(N) : "memory");
}

__device__ __forceinline__ void ldm_x4(uint32_t& r0, uint32_t& r1,
                                       uint32_t& r2, uint32_t& r3, uint32_t a) {
    asm volatile("ldmatrix.sync.aligned.m8n8.x4.shared.b16 {%0,%1,%2,%3}, [%4];"
                 : "=r"(r0), "=r"(r1), "=r"(r2), "=r"(r3) : "r"(a));
}

// fp16 inputs + fp16 accumulators (2 D-regs).
__device__ __forceinline__ void mma_f16(uint32_t* d, uint32_t a0, uint32_t a1,
                                        uint32_t a2, uint32_t a3,
                                        uint32_t b0, uint32_t b1) {
    asm volatile(
        "mma.sync.aligned.m16n8k16.row.col.f16.f16.f16.f16 "
        "{%0,%1}, {%2,%3,%4,%5}, {%6,%7}, {%0,%1};"
        : "+r"(d[0]), "+r"(d[1])
        : "r"(a0), "r"(a1), "r"(a2), "r"(a3), "r"(b0), "r"(b1));
}

__device__ __forceinline__ uint32_t fkey(float f) {
    uint32_t u = __float_as_uint(f);
    return (u & 0x80000000u) ? ~u : (u | 0x80000000u);
}
__device__ __forceinline__ float fdec(uint32_t k) {
    uint32_t u = (k & 0x80000000u) ? (k ^ 0x80000000u) : ~k;
    return __uint_as_float(u);
}

// ---------------------------------------------------------------------------
__global__ void tofp16_kernel(const float* __restrict__ in,
                              __half* __restrict__ outp, int n4) {
    int i = blockIdx.x * blockDim.x + threadIdx.x;
    if (i >= n4) return;
    float4 v = ((const float4*)in)[i];
    ((__half2*)outp)[2 * i]     = __floats2half2_rn(v.x, v.y);
    ((__half2*)outp)[2 * i + 1] = __floats2half2_rn(v.z, v.w);
}

// Codebook prep: fp16 convert + c2 in one pass. One warp per code row.
__global__ void cbprep_kernel(const float* __restrict__ cb,
                              __half* __restrict__ outp, int N) {
    int row  = (blockIdx.x * blockDim.x + threadIdx.x) >> 5;
    int lane = threadIdx.x & 31;
    if (row >= N) return;
    const float4* r4 = (const float4*)(cb + (size_t)row * DIM);
    float4 v0 = r4[lane * 2], v1 = r4[lane * 2 + 1];
    __half2 h0 = __floats2half2_rn(v0.x, v0.y);
    __half2 h1 = __floats2half2_rn(v0.z, v0.w);
    __half2 h2 = __floats2half2_rn(v1.x, v1.y);
    __half2 h3 = __floats2half2_rn(v1.z, v1.w);
    __half2* o2 = (__half2*)(outp + (size_t)row * DIM);
    o2[lane * 4]     = h0;
    o2[lane * 4 + 1] = h1;
    o2[lane * 4 + 2] = h2;
    o2[lane * 4 + 3] = h3;
    float s = v0.x * v0.x + v0.y * v0.y + v0.z * v0.z + v0.w * v0.w
            + v1.x * v1.x + v1.y * v1.y + v1.z * v1.z + v1.w * v1.w;
#pragma unroll
    for (int o = 16; o > 0; o >>= 1) s += __shfl_xor_sync(0xffffffffu, s, o);
    if (lane == 0) g_c2[row] = s;
}

// ---------------------------------------------------------------------------
// stage one K-chunk: A[128 x 64] (16KB) + B[256 x 64] (32KB) fp16
// ---------------------------------------------------------------------------
__device__ __forceinline__ void stage_ab(uint32_t dst, int m0, int n0,
                                         int kc, int tid) {
#pragma unroll
    for (int i = 0; i < 4; i++) {
        int idx = tid + (i << 8);          // 0..1023
        int c16 = idx & 7;
        int row = idx >> 3;                // 0..127
        cp16(dst + SWZ((uint32_t)(row * 128 + c16 * 16)),
             g_xh + (size_t)(m0 + row) * DIM + kc * KC + c16 * 8);
    }
#pragma unroll
    for (int i = 0; i < 8; i++) {
        int idx = tid + (i << 8);          // 0..2047
        int c16 = idx & 7;
        int row = idx >> 3;                // 0..255
        cp16(dst + 16384 + SWZ((uint32_t)(row * 128 + c16 * 16)),
             g_cbh + (size_t)(n0 + row) * DIM + kc * KC + c16 * 8);
    }
    cp_commit();
}

// ---------------------------------------------------------------------------
// GEMM kernel: one 128x256 tile per CTA, 8 warps (2M x 4N), warp tile 64x64.
// 8 ldm_x4 feed 32 MMAs per k-step (2048 MAC/wavefront). Epilogue ONCE.
// ---------------------------------------------------------------------------
__global__ void __launch_bounds__(256, 2)
gemm_tile_kernel() {
    extern __shared__ char smraw[];
    const uint32_t sb0   = smem_u32(smraw);
    const uint32_t sbase = (sb0 + 1023) & ~1023u;
    char* smp = smraw + (sbase - sb0);

    uint32_t* rowkey = (uint32_t*)(smp + OFF_KEY);
    int*      cnt    = (int*)     (smp + OFF_CNT);
    int*      cand   = (int*)     (smp + OFF_CAND);

    const int tid  = threadIdx.x;
    const int wid  = tid >> 5;
    const int lane = tid & 31;
    const int m0   = blockIdx.x * MBLK;
    const int n0   = blockIdx.y * NTILE;
    const int wm   = (wid & 1) * 64;     // 2 warps in M
    const int wn   = (wid >> 1) * 64;    // 4 warps in N
    const int lrow = lane & 15;
    const int lcol = (lane >> 4) << 4;
    const int g    = lane >> 2;
    const int tg   = lane & 3;

    // Swizzled row bases. Addr(kb) = base ^ kb (kb hits swizzle bits 4..6).
    uint32_t swzA[4], swzB[4];
#pragma unroll
    for (int im = 0; im < 4; im++)
        swzA[im] = SWZ((uint32_t)((wm + im * 16 + lrow) * 128)) ^ (uint32_t)lcol;
#pragma unroll
    for (int bg = 0; bg < 4; bg++)
        swzB[bg] = SWZ((uint32_t)((wn + bg * 16 + lrow) * 128)) ^ (uint32_t)lcol;

    if (tid < 128) { rowkey[tid] = 0xFFFFFFFFu; cnt[tid] = 0; }

    stage_ab(sbase + OFF_BUF, m0, n0, 0, tid);

    // fp16x2 accumulators: [im 0..3][jn 0..7][h 0..1] (h = row-half g/g+8)
    uint32_t acc[4][8][2];
#pragma unroll
    for (int a = 0; a < 4; a++)
#pragma unroll
        for (int b = 0; b < 8; b++) { acc[a][b][0] = 0u; acc[a][b][1] = 0u; }

    uint32_t fa[4][4], fb[4][4];

#pragma unroll
    for (int kc = 0; kc < N_KC; kc++) {
        cp_wait<0>();
        __syncthreads();
        if (kc + 1 < N_KC)
            stage_ab(sbase + OFF_BUF + ((kc + 1) & 1) * STAGE_BYTES,
                     m0, n0, kc + 1, tid);

        const uint32_t pa = sbase + OFF_BUF + (kc & 1) * STAGE_BYTES;
        const uint32_t pb = pa + 16384;

#pragma unroll
        for (int ks = 0; ks < 4; ks++) {
            const uint32_t kb = (uint32_t)(ks * 32);
#pragma unroll
            for (int im = 0; im < 4; im++)
                ldm_x4(fa[im][0], fa[im][1], fa[im][2], fa[im][3],
                       pa + (swzA[im] ^ kb));
#pragma unroll
            for (int bg = 0; bg < 4; bg++)
                ldm_x4(fb[bg][0], fb[bg][1], fb[bg][2], fb[bg][3],
                       pb + (swzB[bg] ^ kb));
#pragma unroll
            for (int im = 0; im < 4; im++)
#pragma unroll
                for (int bg = 0; bg < 4; bg++) {
                    mma_f16(acc[im][bg * 2],     fa[im][0], fa[im][1], fa[im][2], fa[im][3], fb[bg][0], fb[bg][2]);
                    mma_f16(acc[im][bg * 2 + 1], fa[im][0], fa[im][1], fa[im][2], fa[im][3], fb[bg][1], fb[bg][3]);
                }
        }
    }

    // ---- Epilogue (once): tile-local min + candidates -----------------------
    float c2r[8][2];
#pragma unroll
    for (int jn = 0; jn < 8; jn++)
#pragma unroll
        for (int q = 0; q < 2; q++)
            c2r[jn][q] = __ldg(&g_c2[n0 + wn + jn * 8 + tg * 2 + q]);

#pragma unroll
    for (int im = 0; im < 4; im++)
#pragma unroll
        for (int h = 0; h < 2; h++) {
            int r = wm + im * 16 + h * 8 + g;
            float mn = 3.4e38f;
#pragma unroll
            for (int jn = 0; jn < 8; jn++) {
                float2 dv = __half22float2(*(__half2*)&acc[im][jn][h]);
                mn = fminf(mn, fmaf(-2.f, dv.x, c2r[jn][0]));
                mn = fminf(mn, fmaf(-2.f, dv.y, c2r[jn][1]));
            }
            mn = fminf(mn, __shfl_xor_sync(0xffffffffu, mn, 1));
            mn = fminf(mn, __shfl_xor_sync(0xffffffffu, mn, 2));
            if (tg == 0) atomicMin(&rowkey[r], fkey(mn));
        }
    __syncthreads();

#pragma unroll
    for (int im = 0; im < 4; im++)
#pragma unroll
        for (int h = 0; h < 2; h++) {
            int r = wm + im * 16 + h * 8 + g;
            float thr = fdec(rowkey[r]) + MARGIN;
#pragma unroll
            for (int jn = 0; jn < 8; jn++) {
                float2 dv = __half22float2(*(__half2*)&acc[im][jn][h]);
#pragma unroll
                for (int q = 0; q < 2; q++) {
                    float sc = fmaf(-2.f, q ? dv.y : dv.x, c2r[jn][q]);
                    if (sc < thr) {
                        int p = atomicAdd(&cnt[r], 1);
                        if (p < RCAP)
                            cand[r * RCAP + p] = n0 + wn + jn * 8 + tg * 2 + q;
                    }
                }
            }
        }
    __syncthreads();

    // ---- Write 32B record per row ------------------------------------------
    if (tid < 128) {
        int rec[8];
        rec[0] = __float_as_int(fdec(rowkey[tid]));
        rec[1] = cnt[tid];
#pragma unroll
        for (int j = 0; j < RCAP; j++) rec[2 + j] = cand[tid * RCAP + j];
        int* dst = g_rec + ((size_t)(m0 + tid) * N_TILES + blockIdx.y) * 8;
        *(int4*)(dst)     = make_int4(rec[0], rec[1], rec[2], rec[3]);
        *(int4*)(dst + 4) = make_int4(rec[4], rec[5], rec[6], rec[7]);
    }
}

// ---------------------------------------------------------------------------
// Combine: per token, global min over 8 tile records, exact fp32 rescore of
// pruned candidates, gather + SSE partial + index. 128 threads per token.
// ---------------------------------------------------------------------------
__global__ void __launch_bounds__(128)
combine_kernel(const float* __restrict__ x, const float* __restrict__ cb,
               float* __restrict__ out_q, float* __restrict__ out_idx) {
    __shared__ int   recs[N_TILES * 8];
    __shared__ float xs[DIM];
    __shared__ float sgmin;
    __shared__ int   clist[N_TILES * RCAP];
    __shared__ int   ftile[N_TILES];
    __shared__ int   ccnt, fcnt;
    __shared__ unsigned long long sbest;

    const int t = blockIdx.x, tid = threadIdx.x;
    const int wid = tid >> 5, lane = tid & 31;

    if (tid < N_TILES * 2)
        ((int4*)recs)[tid] = ((const int4*)(g_rec + (size_t)t * N_TILES * 8))[tid];
    ((float2*)xs)[tid] = ((const float2*)(x + (size_t)t * DIM))[tid];
    if (tid == 0) { ccnt = 0; fcnt = 0; sbest = ~0ull; }
    __syncthreads();

    if (tid == 0) {
        float gm = 3.4e38f;
#pragma unroll
        for (int i = 0; i < N_TILES; i++)
            gm = fminf(gm, __int_as_float(recs[i * 8]));
        sgmin = gm;
    }
    __syncthreads();
    const float glim = sgmin + MARGIN;

    if (tid < N_TILES) {
        float tmin = __int_as_float(recs[tid * 8]);
        if (tmin <= glim) {
            int c = recs[tid * 8 + 1];
            if (c <= RCAP) {
                for (int j = 0; j < c; j++) {
                    int p = atomicAdd(&ccnt, 1);
                    clist[p] = recs[tid * 8 + 2 + j];
                }
            } else {
                int p = atomicAdd(&fcnt, 1);
                ftile[p] = tid;
            }
        }
    }
    __syncthreads();

    // exact rescore: warp per candidate
    const int nc = ccnt;
    for (int ci = wid; ci < nc; ci += 4) {
        int n = clist[ci];
        const float* cr = cb + (size_t)n * DIM;
        float dot = 0.f;
#pragma unroll
        for (int j = 0; j < 8; j++)
            dot = fmaf(xs[lane + j * 32], cr[lane + j * 32], dot);
#pragma unroll
        for (int o = 16; o > 0; o >>= 1)
            dot += __shfl_xor_sync(0xffffffffu, dot, o);
        if (lane == 0) {
            float sv = __ldg(&g_c2[n]) - 2.f * dot;
            unsigned long long key =
                ((unsigned long long)fkey(sv) << 32) | (uint32_t)n;
            atomicMin(&sbest, key);
        }
    }

    // overflowed tiles (rare): exact rescan of the tile's 256 codes
    const int nf = fcnt;
    for (int fi = 0; fi < nf; fi++) {
        int base = ftile[fi] * NTILE;
        for (int cc = wid; cc < NTILE; cc += 4) {
            int n = base + cc;
            const float* cr = cb + (size_t)n * DIM;
            float dot = 0.f;
#pragma unroll
            for (int j = 0; j < 8; j++)
                dot = fmaf(xs[lane + j * 32], cr[lane + j * 32], dot);
#pragma unroll
            for (int o = 16; o > 0; o >>= 1)
                dot += __shfl_xor_sync(0xffffffffu, dot, o);
            if (lane == 0) {
                float sv = __ldg(&g_c2[n]) - 2.f * dot;
                unsigned long long key =
                    ((unsigned long long)fkey(sv) << 32) | (uint32_t)n;
                atomicMin(&sbest, key);
            }
        }
    }
    __syncthreads();
    const int best = (int)(sbest & 0xFFFFFFFFull);

    // gather + SSE partial
    float2 c2v = ((const float2*)(cb + (size_t)best * DIM))[tid];
    ((float2*)(out_q + (size_t)t * DIM))[tid] = c2v;
    float2 xv = ((const float2*)xs)[tid];
    float dx = xv.x - c2v.x, dy = xv.y - c2v.y;
    float d = dx * dx + dy * dy;
#pragma unroll
    for (int o = 16; o > 0; o >>= 1) d += __shfl_xor_sync(0xffffffffu, d, o);
    __shared__ float red[4];
    if (lane == 0) red[wid] = d;
    __syncthreads();
    if (tid == 0) {
        g_partial[t] = red[0] + red[1] + red[2] + red[3];
        out_idx[t]   = (float)best;
    }
}

// ---------------------------------------------------------------------------
__global__ void loss_kernel(float* __restrict__ out_loss, int n4, float inv_count) {
    __shared__ float red[32];
    const int tid = threadIdx.x;
    float s = 0.f;
    const float4* p4 = (const float4*)g_partial;
    for (int i = tid; i < n4; i += 1024) {
        float4 v = p4[i];
        s += v.x + v.y + v.z + v.w;
    }
#pragma unroll
    for (int o = 16; o > 0; o >>= 1) s += __shfl_xor_sync(0xffffffffu, s, o);
    if ((tid & 31) == 0) red[tid >> 5] = s;
    __syncthreads();
    if (tid < 32) {
        float v = red[tid];
#pragma unroll
        for (int o = 16; o > 0; o >>= 1) v += __shfl_xor_sync(0xffffffffu, v, o);
        if (tid == 0) *out_loss = 2.f * v * inv_count;
    }
}

// ---------------------------------------------------------------------------
extern "C" void kernel_launch(void* const* d_in, const int* in_sizes, int n_in,
                              void* d_out, int out_size) {
    const float* x  = (const float*)d_in[0];
    const float* cb = (const float*)d_in[1];
    float* out = (float*)d_out;

    const int bt = in_sizes[0] / DIM;   // 32768
    const int nc = in_sizes[1] / DIM;   // 2048

    const long long need = (long long)bt * DIM + bt + 1;
    const bool full_layout = ((long long)out_size >= need);
    float* out_idx  = full_layout ? (out + (size_t)bt * DIM) : g_dummy;
    float* out_loss = full_layout ? (out + (size_t)bt * DIM + bt) : (g_dummy + BT);

    __half* xh;  cudaGetSymbolAddress((void**)&xh,  g_xh);
    __half* cbh; cudaGetSymbolAddress((void**)&cbh, g_cbh);

    const int nx4 = bt * DIM / 4;
    tofp16_kernel<<<(nx4 + 255) / 256, 256>>>(x, xh, nx4);
    cbprep_kernel<<<(nc * 32 + 255) / 256, 256>>>(cb, cbh, nc);

    cudaFuncSetAttribute(gemm_tile_kernel,
                         cudaFuncAttributeMaxDynamicSharedMemorySize, SMEM_BYTES);
    dim3 grid(bt / MBLK, nc / NTILE);
    gemm_tile_kernel<<<grid, 256, SMEM_BYTES>>>();

    combine_kernel<<<bt, 128>>>(x, cb, out, out_idx);
    loss_kernel<<<1, 1024>>>(out_loss, bt / 4, 1.f / ((float)bt * (float)DIM));
}

// round 15
// speedup vs baseline: 1.0888x; 1.0763x over previous
#include <cuda_runtime.h>
#include <cuda_fp16.h>
#include <cstdint>

#define DIM     256
#define BT      32768
#define NCODE   2048
#define MARGIN  3.0f
#define RCAP    6                  // candidates per row per tile record
#define MBLK    128
#define NTILE   256
#define N_TILES (NCODE / NTILE)    // 8
#define KC      64                 // dims per K-chunk
#define N_KC    (DIM / KC)         // 4
#define STAGE_BYTES 49152          // A 16KB + B 32KB

// GEMM smem layout (relative to 1KB-aligned base)
#define OFF_BUF  0                 // 2 stages x 48 KB
#define OFF_KEY  98304             // u32[128]
#define OFF_CNT  98816             // int[128]
#define OFF_CAND 99328             // int[128][RCAP] = 3072
#define SMEM_BYTES (99328 + 128 * RCAP * 4 + 1024)

// ---------------------------------------------------------------------------
__device__ __half g_xh [(size_t)BT * DIM];      // 16 MB
__device__ __half g_cbh[(size_t)NCODE * DIM];   // 1 MB
__device__ float g_c2[NCODE];
__device__ int   g_rec[(size_t)BT * N_TILES * 8];   // 8 MB: {minf,cnt,cand[6]}
__device__ float g_partial[BT / 8];                 // per-combine-block partial
__device__ float g_dummy[BT + 1];

// ---------------------------------------------------------------------------
__device__ __forceinline__ uint32_t smem_u32(const void* p) {
    uint32_t a;
    asm("{ .reg .u64 t; cvta.to.shared.u64 t, %1; cvt.u32.u64 %0, t; }"
        : "=r"(a) : "l"(p));
    return a;
}

#define SWZ(o) ((o) ^ (((o) >> 3) & 0x70))

__device__ __forceinline__ void cp16(uint32_t d, const void* s) {
    asm volatile("cp.async.cg.shared.global [%0], [%1], 16;\n"
                 :: "r"(d), "l"(__cvta_generic_to_global(s)));
}
__device__ __forceinline__ void cp_commit() {
    asm volatile("cp.async.commit_group;\n" ::: "memory");
}
template <int N> __device__ __forceinline__ void cp_wait() {
    asm volatile("cp.async.wait_group %0;\n" :: "n"(N) : "memory");
}

__device__ __forceinline__ void ldm_x4(uint32_t& r0, uint32_t& r1,
                                       uint32_t& r2, uint32_t& r3, uint32_t a) {
    asm volatile("ldmatrix.sync.aligned.m8n8.x4.shared.b16 {%0,%1,%2,%3}, [%4];"
                 : "=r"(r0), "=r"(r1), "=r"(r2), "=r"(r3) : "r"(a));
}

// fp16 inputs + fp16 accumulators (2 D-regs).
__device__ __forceinline__ void mma_f16(uint32_t* d, uint32_t a0, uint32_t a1,
                                        uint32_t a2, uint32_t a3,
                                        uint32_t b0, uint32_t b1) {
    asm volatile(
        "mma.sync.aligned.m16n8k16.row.col.f16.f16.f16.f16 "
        "{%0,%1}, {%2,%3,%4,%5}, {%6,%7}, {%0,%1};"
        : "+r"(d[0]), "+r"(d[1])
        : "r"(a0), "r"(a1), "r"(a2), "r"(a3), "r"(b0), "r"(b1));
}

__device__ __forceinline__ uint32_t fkey(float f) {
    uint32_t u = __float_as_uint(f);
    return (u & 0x80000000u) ? ~u : (u | 0x80000000u);
}
__device__ __forceinline__ float fdec(uint32_t k) {
    uint32_t u = (k & 0x80000000u) ? (k ^ 0x80000000u) : ~k;
    return __uint_as_float(u);
}

// ---------------------------------------------------------------------------
__global__ void tofp16_kernel(const float* __restrict__ in,
                              __half* __restrict__ outp, int n4) {
    int i = blockIdx.x * blockDim.x + threadIdx.x;
    if (i >= n4) return;
    float4 v = ((const float4*)in)[i];
    ((__half2*)outp)[2 * i]     = __floats2half2_rn(v.x, v.y);
    ((__half2*)outp)[2 * i + 1] = __floats2half2_rn(v.z, v.w);
}

// Codebook prep: fp16 convert + c2 in one pass. One warp per code row.
__global__ void cbprep_kernel(const float* __restrict__ cb,
                              __half* __restrict__ outp, int N) {
    int row  = (blockIdx.x * blockDim.x + threadIdx.x) >> 5;
    int lane = threadIdx.x & 31;
    if (row >= N) return;
    const float4* r4 = (const float4*)(cb + (size_t)row * DIM);
    float4 v0 = r4[lane * 2], v1 = r4[lane * 2 + 1];
    __half2* o2 = (__half2*)(outp + (size_t)row * DIM);
    o2[lane * 4]     = __floats2half2_rn(v0.x, v0.y);
    o2[lane * 4 + 1] = __floats2half2_rn(v0.z, v0.w);
    o2[lane * 4 + 2] = __floats2half2_rn(v1.x, v1.y);
    o2[lane * 4 + 3] = __floats2half2_rn(v1.z, v1.w);
    float s = v0.x * v0.x + v0.y * v0.y + v0.z * v0.z + v0.w * v0.w
            + v1.x * v1.x + v1.y * v1.y + v1.z * v1.z + v1.w * v1.w;
#pragma unroll
    for (int o = 16; o > 0; o >>= 1) s += __shfl_xor_sync(0xffffffffu, s, o);
    if (lane == 0) g_c2[row] = s;
}

// ---------------------------------------------------------------------------
// stage one K-chunk: A[128 x 64] (16KB) + B[256 x 64] (32KB) fp16
// ---------------------------------------------------------------------------
__device__ __forceinline__ void stage_ab(uint32_t dst, int m0, int n0,
                                         int kc, int tid) {
#pragma unroll
    for (int i = 0; i < 4; i++) {
        int idx = tid + (i << 8);
        int c16 = idx & 7;
        int row = idx >> 3;
        cp16(dst + SWZ((uint32_t)(row * 128 + c16 * 16)),
             g_xh + (size_t)(m0 + row) * DIM + kc * KC + c16 * 8);
    }
#pragma unroll
    for (int i = 0; i < 8; i++) {
        int idx = tid + (i << 8);
        int c16 = idx & 7;
        int row = idx >> 3;
        cp16(dst + 16384 + SWZ((uint32_t)(row * 128 + c16 * 16)),
             g_cbh + (size_t)(n0 + row) * DIM + kc * KC + c16 * 8);
    }
    cp_commit();
}

// ---------------------------------------------------------------------------
// GEMM kernel: one 128x256 tile per CTA, 8 warps (2M x 4N), warp tile 64x64.
// ---------------------------------------------------------------------------
__global__ void __launch_bounds__(256, 2)
gemm_tile_kernel() {
    extern __shared__ char smraw[];
    const uint32_t sb0   = smem_u32(smraw);
    const uint32_t sbase = (sb0 + 1023) & ~1023u;
    char* smp = smraw + (sbase - sb0);

    uint32_t* rowkey = (uint32_t*)(smp + OFF_KEY);
    int*      cnt    = (int*)     (smp + OFF_CNT);
    int*      cand   = (int*)     (smp + OFF_CAND);

    const int tid  = threadIdx.x;
    const int wid  = tid >> 5;
    const int lane = tid & 31;
    const int m0   = blockIdx.x * MBLK;
    const int n0   = blockIdx.y * NTILE;
    const int wm   = (wid & 1) * 64;
    const int wn   = (wid >> 1) * 64;
    const int lrow = lane & 15;
    const int lcol = (lane >> 4) << 4;
    const int g    = lane >> 2;
    const int tg   = lane & 3;

    uint32_t swzA[4], swzB[4];
#pragma unroll
    for (int im = 0; im < 4; im++)
        swzA[im] = SWZ((uint32_t)((wm + im * 16 + lrow) * 128)) ^ (uint32_t)lcol;
#pragma unroll
    for (int bg = 0; bg < 4; bg++)
        swzB[bg] = SWZ((uint32_t)((wn + bg * 16 + lrow) * 128)) ^ (uint32_t)lcol;

    if (tid < 128) { rowkey[tid] = 0xFFFFFFFFu; cnt[tid] = 0; }

    stage_ab(sbase + OFF_BUF, m0, n0, 0, tid);

    uint32_t acc[4][8][2];
#pragma unroll
    for (int a = 0; a < 4; a++)
#pragma unroll
        for (int b = 0; b < 8; b++) { acc[a][b][0] = 0u; acc[a][b][1] = 0u; }

    uint32_t fa[4][4], fb[4][4];

#pragma unroll
    for (int kc = 0; kc < N_KC; kc++) {
        cp_wait<0>();
        __syncthreads();
        if (kc + 1 < N_KC)
            stage_ab(sbase + OFF_BUF + ((kc + 1) & 1) * STAGE_BYTES,
                     m0, n0, kc + 1, tid);

        const uint32_t pa = sbase + OFF_BUF + (kc & 1) * STAGE_BYTES;
        const uint32_t pb = pa + 16384;

#pragma unroll
        for (int ks = 0; ks < 4; ks++) {
            const uint32_t kb = (uint32_t)(ks * 32);
#pragma unroll
            for (int im = 0; im < 4; im++)
                ldm_x4(fa[im][0], fa[im][1], fa[im][2], fa[im][3],
                       pa + (swzA[im] ^ kb));
#pragma unroll
            for (int bg = 0; bg < 4; bg++)
                ldm_x4(fb[bg][0], fb[bg][1], fb[bg][2], fb[bg][3],
                       pb + (swzB[bg] ^ kb));
#pragma unroll
            for (int im = 0; im < 4; im++)
#pragma unroll
                for (int bg = 0; bg < 4; bg++) {
                    mma_f16(acc[im][bg * 2],     fa[im][0], fa[im][1], fa[im][2], fa[im][3], fb[bg][0], fb[bg][2]);
                    mma_f16(acc[im][bg * 2 + 1], fa[im][0], fa[im][1], fa[im][2], fa[im][3], fb[bg][1], fb[bg][3]);
                }
        }
    }

    // ---- Epilogue (once): tile-local min + candidates -----------------------
    float c2r[8][2];
#pragma unroll
    for (int jn = 0; jn < 8; jn++)
#pragma unroll
        for (int q = 0; q < 2; q++)
            c2r[jn][q] = __ldg(&g_c2[n0 + wn + jn * 8 + tg * 2 + q]);

#pragma unroll
    for (int im = 0; im < 4; im++)
#pragma unroll
        for (int h = 0; h < 2; h++) {
            int r = wm + im * 16 + h * 8 + g;
            float mn = 3.4e38f;
#pragma unroll
            for (int jn = 0; jn < 8; jn++) {
                float2 dv = __half22float2(*(__half2*)&acc[im][jn][h]);
                mn = fminf(mn, fmaf(-2.f, dv.x, c2r[jn][0]));
                mn = fminf(mn, fmaf(-2.f, dv.y, c2r[jn][1]));
            }
            mn = fminf(mn, __shfl_xor_sync(0xffffffffu, mn, 1));
            mn = fminf(mn, __shfl_xor_sync(0xffffffffu, mn, 2));
            if (tg == 0) atomicMin(&rowkey[r], fkey(mn));
        }
    __syncthreads();

#pragma unroll
    for (int im = 0; im < 4; im++)
#pragma unroll
        for (int h = 0; h < 2; h++) {
            int r = wm + im * 16 + h * 8 + g;
            float thr = fdec(rowkey[r]) + MARGIN;
#pragma unroll
            for (int jn = 0; jn < 8; jn++) {
                float2 dv = __half22float2(*(__half2*)&acc[im][jn][h]);
#pragma unroll
                for (int q = 0; q < 2; q++) {
                    float sc = fmaf(-2.f, q ? dv.y : dv.x, c2r[jn][q]);
                    if (sc < thr) {
                        int p = atomicAdd(&cnt[r], 1);
                        if (p < RCAP)
                            cand[r * RCAP + p] = n0 + wn + jn * 8 + tg * 2 + q;
                    }
                }
            }
        }
    __syncthreads();

    if (tid < 128) {
        int rec[8];
        rec[0] = __float_as_int(fdec(rowkey[tid]));
        rec[1] = cnt[tid];
#pragma unroll
        for (int j = 0; j < RCAP; j++) rec[2 + j] = cand[tid * RCAP + j];
        int* dst = g_rec + ((size_t)(m0 + tid) * N_TILES + blockIdx.y) * 8;
        *(int4*)(dst)     = make_int4(rec[0], rec[1], rec[2], rec[3]);
        *(int4*)(dst + 4) = make_int4(rec[4], rec[5], rec[6], rec[7]);
    }
}

// ---------------------------------------------------------------------------
// Combine: ONE WARP PER TOKEN (8 warps / block). No block syncs in the
// per-token path; best tracked lane-redundantly (deterministic order).
// Block-level SSE partial reduced once at the end.
// ---------------------------------------------------------------------------
__global__ void __launch_bounds__(256)
combine_kernel(const float* __restrict__ x, const float* __restrict__ cb,
               float* __restrict__ out_q, float* __restrict__ out_idx) {
    __shared__ int   recs[8][N_TILES * 8];   // 8 warps x 64 ints
    __shared__ float bred[8];

    const int wid  = threadIdx.x >> 5;
    const int lane = threadIdx.x & 31;
    const int t    = blockIdx.x * 8 + wid;

    if (lane < 16)
        ((int4*)recs[wid])[lane] =
            ((const int4*)(g_rec + (size_t)t * N_TILES * 8))[lane];

    const float4* xr = (const float4*)(x + (size_t)t * DIM);
    float4 xv0 = xr[lane * 2], xv1 = xr[lane * 2 + 1];
    __syncwarp();

    // global min over 8 tile minima
    float tm = (lane < N_TILES) ? __int_as_float(recs[wid][lane * 8]) : 3.4e38f;
#pragma unroll
    for (int o = 4; o > 0; o >>= 1)
        tm = fminf(tm, __shfl_xor_sync(0xffffffffu, tm, o));
    const float glim = __shfl_sync(0xffffffffu, tm, 0) + MARGIN;

    float bv = 3.4e38f;
    int   bi = 0x7fffffff;

    for (int tj = 0; tj < N_TILES; tj++) {
        float tmin = __int_as_float(recs[wid][tj * 8]);
        if (tmin > glim) continue;
        int c = recs[wid][tj * 8 + 1];
        if (c <= RCAP) {
            for (int j = 0; j < c; j++) {
                int n = recs[wid][tj * 8 + 2 + j];
                const float4* cr = (const float4*)(cb + (size_t)n * DIM);
                float4 c0 = cr[lane * 2], c1 = cr[lane * 2 + 1];
                float dot = xv0.x * c0.x + xv0.y * c0.y + xv0.z * c0.z + xv0.w * c0.w
                          + xv1.x * c1.x + xv1.y * c1.y + xv1.z * c1.z + xv1.w * c1.w;
#pragma unroll
                for (int o = 16; o > 0; o >>= 1)
                    dot += __shfl_xor_sync(0xffffffffu, dot, o);
                float sv = __ldg(&g_c2[n]) - 2.f * dot;
                if (sv < bv || (sv == bv && n < bi)) { bv = sv; bi = n; }
            }
        } else {
            // overflow (rare): exact rescan of the tile's 256 codes
            for (int cc = 0; cc < NTILE; cc++) {
                int n = tj * NTILE + cc;
                const float4* cr = (const float4*)(cb + (size_t)n * DIM);
                float4 c0 = cr[lane * 2], c1 = cr[lane * 2 + 1];
                float dot = xv0.x * c0.x + xv0.y * c0.y + xv0.z * c0.z + xv0.w * c0.w
                          + xv1.x * c1.x + xv1.y * c1.y + xv1.z * c1.z + xv1.w * c1.w;
#pragma unroll
                for (int o = 16; o > 0; o >>= 1)
                    dot += __shfl_xor_sync(0xffffffffu, dot, o);
                float sv = __ldg(&g_c2[n]) - 2.f * dot;
                if (sv < bv || (sv == bv && n < bi)) { bv = sv; bi = n; }
            }
        }
    }

    // gather + SSE partial (bi identical across lanes)
    const float4* cr = (const float4*)(cb + (size_t)bi * DIM);
    float4 c0 = cr[lane * 2], c1 = cr[lane * 2 + 1];
    float4* qr = (float4*)(out_q + (size_t)t * DIM);
    qr[lane * 2]     = c0;
    qr[lane * 2 + 1] = c1;

    float dx = xv0.x - c0.x, dy = xv0.y - c0.y, dz = xv0.z - c0.z, dw = xv0.w - c0.w;
    float d = dx * dx + dy * dy + dz * dz + dw * dw;
    dx = xv1.x - c1.x; dy = xv1.y - c1.y; dz = xv1.z - c1.z; dw = xv1.w - c1.w;
    d += dx * dx + dy * dy + dz * dz + dw * dw;
#pragma unroll
    for (int o = 16; o > 0; o >>= 1) d += __shfl_xor_sync(0xffffffffu, d, o);
    if (lane == 0) {
        bred[wid] = d;
        out_idx[t] = (float)bi;
    }
    __syncthreads();
    if (threadIdx.x == 0) {
        float s = 0.f;
#pragma unroll
        for (int w = 0; w < 8; w++) s += bred[w];
        g_partial[blockIdx.x] = s;
    }
}

// ---------------------------------------------------------------------------
// Loss: one block reduces BT/8 = 4096 block-partials (one float4 per thread).
// ---------------------------------------------------------------------------
__global__ void loss_kernel(float* __restrict__ out_loss, float inv_count) {
    __shared__ float red[32];
    const int tid = threadIdx.x;
    float4 v = ((const float4*)g_partial)[tid];
    float s = v.x + v.y + v.z + v.w;
#pragma unroll
    for (int o = 16; o > 0; o >>= 1) s += __shfl_xor_sync(0xffffffffu, s, o);
    if ((tid & 31) == 0) red[tid >> 5] = s;
    __syncthreads();
    if (tid < 32) {
        float r = red[tid];
#pragma unroll
        for (int o = 16; o > 0; o >>= 1) r += __shfl_xor_sync(0xffffffffu, r, o);
        if (tid == 0) *out_loss = 2.f * r * inv_count;
    }
}

// ---------------------------------------------------------------------------
extern "C" void kernel_launch(void* const* d_in, const int* in_sizes, int n_in,
                              void* d_out, int out_size) {
    const float* x  = (const float*)d_in[0];
    const float* cb = (const float*)d_in[1];
    float* out = (float*)d_out;

    const int bt = in_sizes[0] / DIM;   // 32768
    const int nc = in_sizes[1] / DIM;   // 2048

    const long long need = (long long)bt * DIM + bt + 1;
    const bool full_layout = ((long long)out_size >= need);
    float* out_idx  = full_layout ? (out + (size_t)bt * DIM) : g_dummy;
    float* out_loss = full_layout ? (out + (size_t)bt * DIM + bt) : (g_dummy + BT);

    __half* xh;  cudaGetSymbolAddress((void**)&xh,  g_xh);
    __half* cbh; cudaGetSymbolAddress((void**)&cbh, g_cbh);

    const int nx4 = bt * DIM / 4;
    tofp16_kernel<<<(nx4 + 255) / 256, 256>>>(x, xh, nx4);
    cbprep_kernel<<<(nc * 32 + 255) / 256, 256>>>(cb, cbh, nc);

    cudaFuncSetAttribute(gemm_tile_kernel,
                         cudaFuncAttributeMaxDynamicSharedMemorySize, SMEM_BYTES);
    dim3 grid(bt / MBLK, nc / NTILE);
    gemm_tile_kernel<<<grid, 256, SMEM_BYTES>>>();

    combine_kernel<<<bt / 8, 256>>>(x, cb, out, out_idx);
    loss_kernel<<<1, 1024>>>(out_loss, 1.f / ((float)bt * (float)DIM));
}

// round 16
// speedup vs baseline: 1.1175x; 1.0263x over previous
#include <cuda_runtime.h>
#include <cuda_fp16.h>
#include <cstdint>

#define DIM     256
#define BT      32768
#define NCODE   2048
#define MARGIN  3.0f
#define RCAP    6                  // candidates per row per tile record
#define MBLK    128
#define NTILE   256
#define N_TILES (NCODE / NTILE)    // 8
#define KC      64                 // dims per K-chunk
#define N_KC    (DIM / KC)         // 4
#define STAGE_BYTES 49152          // A 16KB + B 32KB

// GEMM smem layout (relative to 1KB-aligned base)
#define OFF_BUF  0                 // 2 stages x 48 KB
#define OFF_KEY  98304             // u32[128]
#define OFF_CNT  98816             // int[128]
#define OFF_CAND 99328             // int[128][RCAP] = 3072
#define SMEM_BYTES (99328 + 128 * RCAP * 4 + 1024)

// ---------------------------------------------------------------------------
__device__ __half g_xh [(size_t)BT * DIM];      // 16 MB
__device__ __half g_cbh[(size_t)NCODE * DIM];   // 1 MB
__device__ float g_c2[NCODE];
__device__ int   g_rec[(size_t)BT * N_TILES * 8];   // 8 MB: {minf,cnt,cand[6]}
__device__ float g_partial[BT / 8];                 // per-combine-block partial
__device__ float g_dummy[BT + 1];

// ---------------------------------------------------------------------------
__device__ __forceinline__ uint32_t smem_u32(const void* p) {
    uint32_t a;
    asm("{ .reg .u64 t; cvta.to.shared.u64 t, %1; cvt.u32.u64 %0, t; }"
        : "=r"(a) : "l"(p));
    return a;
}

#define SWZ(o) ((o) ^ (((o) >> 3) & 0x70))

__device__ __forceinline__ void cp16(uint32_t d, const void* s) {
    asm volatile("cp.async.cg.shared.global [%0], [%1], 16;\n"
                 :: "r"(d), "l"(__cvta_generic_to_global(s)));
}
__device__ __forceinline__ void cp_commit() {
    asm volatile("cp.async.commit_group;\n" ::: "memory");
}
template <int N> __device__ __forceinline__ void cp_wait() {
    asm volatile("cp.async.wait_group %0;\n" :: "n"(N) : "memory");
}

__device__ __forceinline__ void ldm_x4(uint32_t& r0, uint32_t& r1,
                                       uint32_t& r2, uint32_t& r3, uint32_t a) {
    asm volatile("ldmatrix.sync.aligned.m8n8.x4.shared.b16 {%0,%1,%2,%3}, [%4];"
                 : "=r"(r0), "=r"(r1), "=r"(r2), "=r"(r3) : "r"(a));
}

// fp16 inputs + fp16 accumulators (2 D-regs).
__device__ __forceinline__ void mma_f16(uint32_t* d, uint32_t a0, uint32_t a1,
                                        uint32_t a2, uint32_t a3,
                                        uint32_t b0, uint32_t b1) {
    asm volatile(
        "mma.sync.aligned.m16n8k16.row.col.f16.f16.f16.f16 "
        "{%0,%1}, {%2,%3,%4,%5}, {%6,%7}, {%0,%1};"
        : "+r"(d[0]), "+r"(d[1])
        : "r"(a0), "r"(a1), "r"(a2), "r"(a3), "r"(b0), "r"(b1));
}

__device__ __forceinline__ uint32_t fkey(float f) {
    uint32_t u = __float_as_uint(f);
    return (u & 0x80000000u) ? ~u : (u | 0x80000000u);
}
__device__ __forceinline__ float fdec(uint32_t k) {
    uint32_t u = (k & 0x80000000u) ? (k ^ 0x80000000u) : ~k;
    return __uint_as_float(u);
}

// ---------------------------------------------------------------------------
// Fused prep: blocks [0, nxb) convert x (elementwise float4);
// blocks [nxb, nxb + nc/8) prep codebook (warp per row: fp16 + c2).
// ---------------------------------------------------------------------------
__global__ void prep_kernel(const float* __restrict__ x,
                            const float* __restrict__ cb,
                            __half* __restrict__ xh,
                            __half* __restrict__ cbh,
                            int n4, int nxb, int N) {
    if ((int)blockIdx.x < nxb) {
        int i = blockIdx.x * 256 + threadIdx.x;
        if (i >= n4) return;
        float4 v = ((const float4*)x)[i];
        ((__half2*)xh)[2 * i]     = __floats2half2_rn(v.x, v.y);
        ((__half2*)xh)[2 * i + 1] = __floats2half2_rn(v.z, v.w);
    } else {
        int row  = (blockIdx.x - nxb) * 8 + (threadIdx.x >> 5);
        int lane = threadIdx.x & 31;
        if (row >= N) return;
        const float4* r4 = (const float4*)(cb + (size_t)row * DIM);
        float4 v0 = r4[lane * 2], v1 = r4[lane * 2 + 1];
        __half2* o2 = (__half2*)(cbh + (size_t)row * DIM);
        o2[lane * 4]     = __floats2half2_rn(v0.x, v0.y);
        o2[lane * 4 + 1] = __floats2half2_rn(v0.z, v0.w);
        o2[lane * 4 + 2] = __floats2half2_rn(v1.x, v1.y);
        o2[lane * 4 + 3] = __floats2half2_rn(v1.z, v1.w);
        float s = v0.x * v0.x + v0.y * v0.y + v0.z * v0.z + v0.w * v0.w
                + v1.x * v1.x + v1.y * v1.y + v1.z * v1.z + v1.w * v1.w;
#pragma unroll
        for (int o = 16; o > 0; o >>= 1) s += __shfl_xor_sync(0xffffffffu, s, o);
        if (lane == 0) g_c2[row] = s;
    }
}

// ---------------------------------------------------------------------------
// stage one K-chunk: A[128 x 64] (16KB) + B[256 x 64] (32KB) fp16
// ---------------------------------------------------------------------------
__device__ __forceinline__ void stage_ab(uint32_t dst, int m0, int n0,
                                         int kc, int tid) {
#pragma unroll
    for (int i = 0; i < 4; i++) {
        int idx = tid + (i << 8);
        int c16 = idx & 7;
        int row = idx >> 3;
        cp16(dst + SWZ((uint32_t)(row * 128 + c16 * 16)),
             g_xh + (size_t)(m0 + row) * DIM + kc * KC + c16 * 8);
    }
#pragma unroll
    for (int i = 0; i < 8; i++) {
        int idx = tid + (i << 8);
        int c16 = idx & 7;
        int row = idx >> 3;
        cp16(dst + 16384 + SWZ((uint32_t)(row * 128 + c16 * 16)),
             g_cbh + (size_t)(n0 + row) * DIM + kc * KC + c16 * 8);
    }
    cp_commit();
}

// ---------------------------------------------------------------------------
// GEMM kernel: one 128x256 tile per CTA, 8 warps (2M x 4N), warp tile 64x64.
// ---------------------------------------------------------------------------
__global__ void __launch_bounds__(256, 2)
gemm_tile_kernel() {
    extern __shared__ char smraw[];
    const uint32_t sb0   = smem_u32(smraw);
    const uint32_t sbase = (sb0 + 1023) & ~1023u;
    char* smp = smraw + (sbase - sb0);

    uint32_t* rowkey = (uint32_t*)(smp + OFF_KEY);
    int*      cnt    = (int*)     (smp + OFF_CNT);
    int*      cand   = (int*)     (smp + OFF_CAND);

    const int tid  = threadIdx.x;
    const int wid  = tid >> 5;
    const int lane = tid & 31;
    const int m0   = blockIdx.x * MBLK;
    const int n0   = blockIdx.y * NTILE;
    const int wm   = (wid & 1) * 64;
    const int wn   = (wid >> 1) * 64;
    const int lrow = lane & 15;
    const int lcol = (lane >> 4) << 4;
    const int g    = lane >> 2;
    const int tg   = lane & 3;

    uint32_t swzA[4], swzB[4];
#pragma unroll
    for (int im = 0; im < 4; im++)
        swzA[im] = SWZ((uint32_t)((wm + im * 16 + lrow) * 128)) ^ (uint32_t)lcol;
#pragma unroll
    for (int bg = 0; bg < 4; bg++)
        swzB[bg] = SWZ((uint32_t)((wn + bg * 16 + lrow) * 128)) ^ (uint32_t)lcol;

    if (tid < 128) { rowkey[tid] = 0xFFFFFFFFu; cnt[tid] = 0; }

    stage_ab(sbase + OFF_BUF, m0, n0, 0, tid);

    uint32_t acc[4][8][2];
#pragma unroll
    for (int a = 0; a < 4; a++)
#pragma unroll
        for (int b = 0; b < 8; b++) { acc[a][b][0] = 0u; acc[a][b][1] = 0u; }

    uint32_t fa[4][4], fb[4][4];

#pragma unroll
    for (int kc = 0; kc < N_KC; kc++) {
        cp_wait<0>();
        __syncthreads();
        if (kc + 1 < N_KC)
            stage_ab(sbase + OFF_BUF + ((kc + 1) & 1) * STAGE_BYTES,
                     m0, n0, kc + 1, tid);

        const uint32_t pa = sbase + OFF_BUF + (kc & 1) * STAGE_BYTES;
        const uint32_t pb = pa + 16384;

#pragma unroll
        for (int ks = 0; ks < 4; ks++) {
            const uint32_t kb = (uint32_t)(ks * 32);
#pragma unroll
            for (int im = 0; im < 4; im++)
                ldm_x4(fa[im][0], fa[im][1], fa[im][2], fa[im][3],
                       pa + (swzA[im] ^ kb));
#pragma unroll
            for (int bg = 0; bg < 4; bg++)
                ldm_x4(fb[bg][0], fb[bg][1], fb[bg][2], fb[bg][3],
                       pb + (swzB[bg] ^ kb));
#pragma unroll
            for (int im = 0; im < 4; im++)
#pragma unroll
                for (int bg = 0; bg < 4; bg++) {
                    mma_f16(acc[im][bg * 2],     fa[im][0], fa[im][1], fa[im][2], fa[im][3], fb[bg][0], fb[bg][2]);
                    mma_f16(acc[im][bg * 2 + 1], fa[im][0], fa[im][1], fa[im][2], fa[im][3], fb[bg][1], fb[bg][3]);
                }
        }
    }

    // ---- Epilogue (once): tile-local min + candidates -----------------------
    float c2r[8][2];
#pragma unroll
    for (int jn = 0; jn < 8; jn++)
#pragma unroll
        for (int q = 0; q < 2; q++)
            c2r[jn][q] = __ldg(&g_c2[n0 + wn + jn * 8 + tg * 2 + q]);

#pragma unroll
    for (int im = 0; im < 4; im++)
#pragma unroll
        for (int h = 0; h < 2; h++) {
            int r = wm + im * 16 + h * 8 + g;
            float mn = 3.4e38f;
#pragma unroll
            for (int jn = 0; jn < 8; jn++) {
                float2 dv = __half22float2(*(__half2*)&acc[im][jn][h]);
                mn = fminf(mn, fmaf(-2.f, dv.x, c2r[jn][0]));
                mn = fminf(mn, fmaf(-2.f, dv.y, c2r[jn][1]));
            }
            mn = fminf(mn, __shfl_xor_sync(0xffffffffu, mn, 1));
            mn = fminf(mn, __shfl_xor_sync(0xffffffffu, mn, 2));
            if (tg == 0) atomicMin(&rowkey[r], fkey(mn));
        }
    __syncthreads();

#pragma unroll
    for (int im = 0; im < 4; im++)
#pragma unroll
        for (int h = 0; h < 2; h++) {
            int r = wm + im * 16 + h * 8 + g;
            float thr = fdec(rowkey[r]) + MARGIN;
#pragma unroll
            for (int jn = 0; jn < 8; jn++) {
                float2 dv = __half22float2(*(__half2*)&acc[im][jn][h]);
#pragma unroll
                for (int q = 0; q < 2; q++) {
                    float sc = fmaf(-2.f, q ? dv.y : dv.x, c2r[jn][q]);
                    if (sc < thr) {
                        int p = atomicAdd(&cnt[r], 1);
                        if (p < RCAP)
                            cand[r * RCAP + p] = n0 + wn + jn * 8 + tg * 2 + q;
                    }
                }
            }
        }
    __syncthreads();

    if (tid < 128) {
        int rec[8];
        rec[0] = __float_as_int(fdec(rowkey[tid]));
        rec[1] = cnt[tid];
#pragma unroll
        for (int j = 0; j < RCAP; j++) rec[2 + j] = cand[tid * RCAP + j];
        int* dst = g_rec + ((size_t)(m0 + tid) * N_TILES + blockIdx.y) * 8;
        *(int4*)(dst)     = make_int4(rec[0], rec[1], rec[2], rec[3]);
        *(int4*)(dst + 4) = make_int4(rec[4], rec[5], rec[6], rec[7]);
    }
}

// ---------------------------------------------------------------------------
// Combine: ONE WARP PER TOKEN. Fast path: if the surviving tiles hold exactly
// one candidate total (no overflow), it IS the argmin (true best is always in
// the superset) -> skip the rescore entirely.
// ---------------------------------------------------------------------------
__global__ void __launch_bounds__(256)
combine_kernel(const float* __restrict__ x, const float* __restrict__ cb,
               float* __restrict__ out_q, float* __restrict__ out_idx) {
    __shared__ int   recs[8][N_TILES * 8];
    __shared__ float bred[8];

    const int wid  = threadIdx.x >> 5;
    const int lane = threadIdx.x & 31;
    const int t    = blockIdx.x * 8 + wid;

    if (lane < 16)
        ((int4*)recs[wid])[lane] =
            ((const int4*)(g_rec + (size_t)t * N_TILES * 8))[lane];

    const float4* xr = (const float4*)(x + (size_t)t * DIM);
    float4 xv0 = xr[lane * 2], xv1 = xr[lane * 2 + 1];
    __syncwarp();

    // global min over 8 tile minima
    float tm = (lane < N_TILES) ? __int_as_float(recs[wid][lane * 8]) : 3.4e38f;
#pragma unroll
    for (int o = 4; o > 0; o >>= 1)
        tm = fminf(tm, __shfl_xor_sync(0xffffffffu, tm, o));
    const float glim = __shfl_sync(0xffffffffu, tm, 0) + MARGIN;

    // census: total candidates + overflow flag (lane-redundant, deterministic)
    int tot = 0, ovf = 0, firstc = -1;
#pragma unroll
    for (int tj = 0; tj < N_TILES; tj++) {
        float tmin = __int_as_float(recs[wid][tj * 8]);
        if (tmin > glim) continue;
        int c = recs[wid][tj * 8 + 1];
        if (c > RCAP) { ovf = 1; }
        else {
            if (firstc < 0 && c > 0) firstc = recs[wid][tj * 8 + 2];
            tot += c;
        }
    }

    int bi;
    if (!ovf && tot == 1) {
        bi = firstc;                     // fast path: unique candidate == argmin
    } else {
        float bv = 3.4e38f;
        bi = 0x7fffffff;
        for (int tj = 0; tj < N_TILES; tj++) {
            float tmin = __int_as_float(recs[wid][tj * 8]);
            if (tmin > glim) continue;
            int c = recs[wid][tj * 8 + 1];
            if (c <= RCAP) {
                for (int j = 0; j < c; j++) {
                    int n = recs[wid][tj * 8 + 2 + j];
                    const float4* cr = (const float4*)(cb + (size_t)n * DIM);
                    float4 c0 = cr[lane * 2], c1 = cr[lane * 2 + 1];
                    float dot = xv0.x * c0.x + xv0.y * c0.y + xv0.z * c0.z + xv0.w * c0.w
                              + xv1.x * c1.x + xv1.y * c1.y + xv1.z * c1.z + xv1.w * c1.w;
#pragma unroll
                    for (int o = 16; o > 0; o >>= 1)
                        dot += __shfl_xor_sync(0xffffffffu, dot, o);
                    float sv = __ldg(&g_c2[n]) - 2.f * dot;
                    if (sv < bv || (sv == bv && n < bi)) { bv = sv; bi = n; }
                }
            } else {
                for (int cc = 0; cc < NTILE; cc++) {
                    int n = tj * NTILE + cc;
                    const float4* cr = (const float4*)(cb + (size_t)n * DIM);
                    float4 c0 = cr[lane * 2], c1 = cr[lane * 2 + 1];
                    float dot = xv0.x * c0.x + xv0.y * c0.y + xv0.z * c0.z + xv0.w * c0.w
                              + xv1.x * c1.x + xv1.y * c1.y + xv1.z * c1.z + xv1.w * c1.w;
#pragma unroll
                    for (int o = 16; o > 0; o >>= 1)
                        dot += __shfl_xor_sync(0xffffffffu, dot, o);
                    float sv = __ldg(&g_c2[n]) - 2.f * dot;
                    if (sv < bv || (sv == bv && n < bi)) { bv = sv; bi = n; }
                }
            }
        }
    }

    // gather + SSE partial (bi identical across lanes)
    const float4* cr = (const float4*)(cb + (size_t)bi * DIM);
    float4 c0 = cr[lane * 2], c1 = cr[lane * 2 + 1];
    float4* qr = (float4*)(out_q + (size_t)t * DIM);
    qr[lane * 2]     = c0;
    qr[lane * 2 + 1] = c1;

    float dx = xv0.x - c0.x, dy = xv0.y - c0.y, dz = xv0.z - c0.z, dw = xv0.w - c0.w;
    float d = dx * dx + dy * dy + dz * dz + dw * dw;
    dx = xv1.x - c1.x; dy = xv1.y - c1.y; dz = xv1.z - c1.z; dw = xv1.w - c1.w;
    d += dx * dx + dy * dy + dz * dz + dw * dw;
#pragma unroll
    for (int o = 16; o > 0; o >>= 1) d += __shfl_xor_sync(0xffffffffu, d, o);
    if (lane == 0) {
        bred[wid] = d;
        out_idx[t] = (float)bi;
    }
    __syncthreads();
    if (threadIdx.x == 0) {
        float s = 0.f;
#pragma unroll
        for (int w = 0; w < 8; w++) s += bred[w];
        g_partial[blockIdx.x] = s;
    }
}

// ---------------------------------------------------------------------------
// Loss: one block reduces BT/8 = 4096 block-partials (one float4 per thread).
// ---------------------------------------------------------------------------
__global__ void loss_kernel(float* __restrict__ out_loss, float inv_count) {
    __shared__ float red[32];
    const int tid = threadIdx.x;
    float4 v = ((const float4*)g_partial)[tid];
    float s = v.x + v.y + v.z + v.w;
#pragma unroll
    for (int o = 16; o > 0; o >>= 1) s += __shfl_xor_sync(0xffffffffu, s, o);
    if ((tid & 31) == 0) red[tid >> 5] = s;
    __syncthreads();
    if (tid < 32) {
        float r = red[tid];
#pragma unroll
        for (int o = 16; o > 0; o >>= 1) r += __shfl_xor_sync(0xffffffffu, r, o);
        if (tid == 0) *out_loss = 2.f * r * inv_count;
    }
}

// ---------------------------------------------------------------------------
extern "C" void kernel_launch(void* const* d_in, const int* in_sizes, int n_in,
                              void* d_out, int out_size) {
    const float* x  = (const float*)d_in[0];
    const float* cb = (const float*)d_in[1];
    float* out = (float*)d_out;

    const int bt = in_sizes[0] / DIM;   // 32768
    const int nc = in_sizes[1] / DIM;   // 2048

    const long long need = (long long)bt * DIM + bt + 1;
    const bool full_layout = ((long long)out_size >= need);
    float* out_idx  = full_layout ? (out + (size_t)bt * DIM) : g_dummy;
    float* out_loss = full_layout ? (out + (size_t)bt * DIM + bt) : (g_dummy + BT);

    __half* xh;  cudaGetSymbolAddress((void**)&xh,  g_xh);
    __half* cbh; cudaGetSymbolAddress((void**)&cbh, g_cbh);

    const int nx4 = bt * DIM / 4;
    const int nxb = (nx4 + 255) / 256;
    const int ncb = (nc + 7) / 8;
    prep_kernel<<<nxb + ncb, 256>>>(x, cb, xh, cbh, nx4, nxb, nc);

    cudaFuncSetAttribute(gemm_tile_kernel,
                         cudaFuncAttributeMaxDynamicSharedMemorySize, SMEM_BYTES);
    dim3 grid(bt / MBLK, nc / NTILE);
    gemm_tile_kernel<<<grid, 256, SMEM_BYTES>>>();

    combine_kernel<<<bt / 8, 256>>>(x, cb, out, out_idx);
    loss_kernel<<<1, 1024>>>(out_loss, 1.f / ((float)bt * (float)DIM));
}